// round 1
// baseline (speedup 1.0000x reference)
#include <cuda_runtime.h>
#include <math.h>

#define MAXN 100000
#define MAXE 1600000
#define EPS 1e-16f

// ------------------------ scratch (device globals, no allocs) ---------------
__device__ float g_h1[MAXN * 128];     // layer-1 node projections
__device__ float g_out1[MAXN * 128];   // layer-1 aggregated output (pre-ELU)
__device__ float g_asrc1[MAXN * 2];
__device__ float g_adst1[MAXN * 2];
__device__ float g_nmax1[MAXN * 2];
__device__ float g_den1[MAXN * 2];     // denom, then overwritten with 1/(denom+eps)
__device__ float g_eself1[MAXN * 2];
__device__ float g_alpha1[MAXE * 2];   // raw alpha, then exp(alpha-max)

__device__ float g_h2p[MAXN * 2];      // layer-2 node projections
__device__ float g_asrc2[MAXN];
__device__ float g_adst2[MAXN];
__device__ float g_nmax2[MAXN];
__device__ float g_den2[MAXN];
__device__ float g_eself2[MAXN];
__device__ float g_alpha2[MAXE];

__device__ float g_weatt1[6];          // [head][k] folded edge-attention weights
__device__ float g_weatt2[3];

// ------------------------ helpers -------------------------------------------
static __device__ __forceinline__ float leaky(float a) { return a > 0.f ? a : 0.2f * a; }

static __device__ __forceinline__ void atomicMaxFloat(float* addr, float v) {
    if (v >= 0.f) atomicMax((int*)addr, __float_as_int(v));
    else          atomicMin((unsigned int*)addr, __float_as_uint(v));
}

static __device__ __forceinline__ void redAddV4(float* p, float a, float b, float c, float d) {
    asm volatile("red.global.add.v4.f32 [%0], {%1,%2,%3,%4};"
                 :: "l"(p), "f"(a), "f"(b), "f"(c), "f"(d) : "memory");
}
static __device__ __forceinline__ void redAddV2(float* p, float a, float b) {
    asm volatile("red.global.add.v2.f32 [%0], {%1,%2};"
                 :: "l"(p), "f"(a), "f"(b) : "memory");
}

// ------------------------ K0: fold edge-attention weights -------------------
__global__ void k_pre(const float* __restrict__ We1, const float* __restrict__ ae1,
                      const float* __restrict__ We2, const float* __restrict__ ae2) {
    if (blockIdx.x == 0 && threadIdx.x == 0) {
        for (int h = 0; h < 2; h++)
            for (int k = 0; k < 3; k++) {
                float s = 0.f;
                for (int c = 0; c < 64; c++) s += We1[k * 128 + h * 64 + c] * ae1[h * 64 + c];
                g_weatt1[h * 3 + k] = s;
            }
        for (int k = 0; k < 3; k++)
            g_weatt2[k] = We2[k * 2 + 0] * ae2[0] + We2[k * 2 + 1] * ae2[1];
    }
}

// ------------------------ K1: h1 = x @ W1 (M=N,128x128) ---------------------
#define BM 64
__global__ __launch_bounds__(256) void k_gemm1(const float* __restrict__ x,
                                               const float* __restrict__ W, int N) {
    __shared__ float xs[BM][33];
    __shared__ float ws[32][128];
    const int tid = threadIdx.x;
    const int tx = tid & 31, ty = tid >> 5;
    const int c0 = tx * 4, r0 = ty * 8;
    const int rowBase = blockIdx.x * BM;

    float acc[8][4];
#pragma unroll
    for (int i = 0; i < 8; i++) { acc[i][0] = acc[i][1] = acc[i][2] = acc[i][3] = 0.f; }

    for (int k0 = 0; k0 < 128; k0 += 32) {
        for (int i = tid; i < BM * 32; i += 256) {
            int r = i >> 5, c = i & 31;
            int gr = rowBase + r;
            xs[r][c] = (gr < N) ? x[(long)gr * 128 + k0 + c] : 0.f;
        }
        for (int i = tid; i < 32 * 128 / 4; i += 256) {
            int idx = i * 4;
            int r = idx >> 7, c = idx & 127;
            *(float4*)&ws[r][c] = *(const float4*)&W[(k0 + r) * 128 + c];
        }
        __syncthreads();
#pragma unroll
        for (int kk = 0; kk < 32; kk++) {
            float b0 = ws[kk][c0], b1 = ws[kk][c0 + 1], b2 = ws[kk][c0 + 2], b3 = ws[kk][c0 + 3];
#pragma unroll
            for (int i = 0; i < 8; i++) {
                float a = xs[r0 + i][kk];
                acc[i][0] += a * b0; acc[i][1] += a * b1;
                acc[i][2] += a * b2; acc[i][3] += a * b3;
            }
        }
        __syncthreads();
    }
#pragma unroll
    for (int i = 0; i < 8; i++) {
        int gr = rowBase + r0 + i;
        if (gr < N)
            *(float4*)&g_h1[(long)gr * 128 + c0] =
                make_float4(acc[i][0], acc[i][1], acc[i][2], acc[i][3]);
    }
}

// ------------------------ K1b: per-node attention dots (layer 1) ------------
__global__ __launch_bounds__(256) void k_att1(const float* __restrict__ as1,
                                              const float* __restrict__ ad1, int N) {
    int w = (blockIdx.x * blockDim.x + threadIdx.x) >> 5;
    int lane = threadIdx.x & 31;
    if (w >= N) return;
    int c = lane * 4;
    float4 hv = *(const float4*)&g_h1[(long)w * 128 + c];
    float4 s4 = *(const float4*)&as1[c];
    float4 d4 = *(const float4*)&ad1[c];
    float ps = hv.x * s4.x + hv.y * s4.y + hv.z * s4.z + hv.w * s4.w;
    float pd = hv.x * d4.x + hv.y * d4.y + hv.z * d4.z + hv.w * d4.w;
#pragma unroll
    for (int off = 8; off; off >>= 1) {
        ps += __shfl_xor_sync(0xffffffffu, ps, off);
        pd += __shfl_xor_sync(0xffffffffu, pd, off);
    }
    if ((lane & 15) == 0) {
        int h = lane >> 4;
        g_asrc1[w * 2 + h] = ps;
        g_adst1[w * 2 + h] = pd;
    }
}

// ------------------------ layer-1 softmax passes -----------------------------
__global__ __launch_bounds__(256) void k_init_max1(int N) {
    int n = blockIdx.x * blockDim.x + threadIdx.x;
    if (n >= N) return;
#pragma unroll
    for (int h = 0; h < 2; h++)
        g_nmax1[n * 2 + h] = leaky(g_asrc1[n * 2 + h] + g_adst1[n * 2 + h]);
}

__global__ __launch_bounds__(256) void k_alpha1(const int* __restrict__ ei,
                                                const float* __restrict__ ea, int E) {
    int e = blockIdx.x * blockDim.x + threadIdx.x;
    if (e >= E) return;
    int s = ei[e], d = ei[E + e];
    float e0 = ea[e * 3], e1 = ea[e * 3 + 1], e2 = ea[e * 3 + 2];
    float2 asv = *(const float2*)&g_asrc1[s * 2];
    float2 adv = *(const float2*)&g_adst1[d * 2];
#pragma unroll
    for (int h = 0; h < 2; h++) {
        float a = (h ? asv.y : asv.x) + (h ? adv.y : adv.x)
                + e0 * g_weatt1[h * 3] + e1 * g_weatt1[h * 3 + 1] + e2 * g_weatt1[h * 3 + 2];
        a = leaky(a);
        g_alpha1[e * 2 + h] = a;
        atomicMaxFloat(&g_nmax1[d * 2 + h], a);
    }
}

__global__ __launch_bounds__(256) void k_expinit1(int N) {
    int n = blockIdx.x * blockDim.x + threadIdx.x;
    if (n >= N) return;
#pragma unroll
    for (int h = 0; h < 2; h++) {
        float a = leaky(g_asrc1[n * 2 + h] + g_adst1[n * 2 + h]);
        float es = __expf(a - g_nmax1[n * 2 + h]);
        g_eself1[n * 2 + h] = es;
        g_den1[n * 2 + h] = es;
    }
}

__global__ __launch_bounds__(256) void k_expsum1(const int* __restrict__ ei, int E) {
    int e = blockIdx.x * blockDim.x + threadIdx.x;
    if (e >= E) return;
    int d = ei[E + e];
#pragma unroll
    for (int h = 0; h < 2; h++) {
        float ae = __expf(g_alpha1[e * 2 + h] - g_nmax1[d * 2 + h]);
        g_alpha1[e * 2 + h] = ae;
        atomicAdd(&g_den1[d * 2 + h], ae);
    }
}

// self-loop contribution + rinv precompute
__global__ __launch_bounds__(256) void k_agginit1(int N) {
    int w = (blockIdx.x * blockDim.x + threadIdx.x) >> 5;
    int lane = threadIdx.x & 31;
    if (w >= N) return;
    int c = lane * 4;
    int h = c >> 6;
    float dv = g_den1[w * 2 + h];
    float es = g_eself1[w * 2 + h];
    __syncwarp();
    float r = 1.f / (dv + EPS);
    if ((lane & 15) == 0) g_den1[w * 2 + h] = r;
    float sc = es * r;
    float4 hv = *(const float4*)&g_h1[(long)w * 128 + c];
    *(float4*)&g_out1[(long)w * 128 + c] =
        make_float4(hv.x * sc, hv.y * sc, hv.z * sc, hv.w * sc);
}

// one warp per edge: out1[dst] += h1[src] * alpha
__global__ __launch_bounds__(256) void k_agg1(const int* __restrict__ ei, int E) {
    int w = (blockIdx.x * blockDim.x + threadIdx.x) >> 5;
    if (w >= E) return;
    int lane = threadIdx.x & 31;
    int s = ei[w], d = ei[E + w];
    int h = lane >> 4;
    float a = g_alpha1[w * 2 + h] * g_den1[d * 2 + h];
    float4 hv = *(const float4*)&g_h1[(long)s * 128 + lane * 4];
    float* p = &g_out1[(long)d * 128 + lane * 4];
    redAddV4(p, hv.x * a, hv.y * a, hv.z * a, hv.w * a);
}

// ------------------------ K5: ELU + layer-2 projection ----------------------
__global__ __launch_bounds__(256) void k_elu_proj2(const float* __restrict__ b1,
                                                   const float* __restrict__ W2,
                                                   const float* __restrict__ as2,
                                                   const float* __restrict__ ad2, int N) {
    int w = (blockIdx.x * blockDim.x + threadIdx.x) >> 5;
    int lane = threadIdx.x & 31;
    if (w >= N) return;
    int c = lane * 4;
    float4 v = *(const float4*)&g_out1[(long)w * 128 + c];
    v.x += b1[c]; v.y += b1[c + 1]; v.z += b1[c + 2]; v.w += b1[c + 3];
    v.x = v.x > 0.f ? v.x : expm1f(v.x);
    v.y = v.y > 0.f ? v.y : expm1f(v.y);
    v.z = v.z > 0.f ? v.z : expm1f(v.z);
    v.w = v.w > 0.f ? v.w : expm1f(v.w);
    float p0 = v.x * W2[c * 2]       + v.y * W2[(c + 1) * 2]
             + v.z * W2[(c + 2) * 2] + v.w * W2[(c + 3) * 2];
    float p1 = v.x * W2[c * 2 + 1]       + v.y * W2[(c + 1) * 2 + 1]
             + v.z * W2[(c + 2) * 2 + 1] + v.w * W2[(c + 3) * 2 + 1];
#pragma unroll
    for (int off = 16; off; off >>= 1) {
        p0 += __shfl_xor_sync(0xffffffffu, p0, off);
        p1 += __shfl_xor_sync(0xffffffffu, p1, off);
    }
    if (lane == 0) {
        g_h2p[w * 2] = p0;
        g_h2p[w * 2 + 1] = p1;
        g_asrc2[w] = p0 * as2[0] + p1 * as2[1];
        g_adst2[w] = p0 * ad2[0] + p1 * ad2[1];
    }
}

// ------------------------ layer-2 softmax passes -----------------------------
__global__ __launch_bounds__(256) void k_init_max2(int N) {
    int n = blockIdx.x * blockDim.x + threadIdx.x;
    if (n >= N) return;
    g_nmax2[n] = leaky(g_asrc2[n] + g_adst2[n]);
}

__global__ __launch_bounds__(256) void k_alpha2(const int* __restrict__ ei,
                                                const float* __restrict__ ea, int E) {
    int e = blockIdx.x * blockDim.x + threadIdx.x;
    if (e >= E) return;
    int s = ei[e], d = ei[E + e];
    float a = g_asrc2[s] + g_adst2[d]
            + ea[e * 3] * g_weatt2[0] + ea[e * 3 + 1] * g_weatt2[1] + ea[e * 3 + 2] * g_weatt2[2];
    a = leaky(a);
    g_alpha2[e] = a;
    atomicMaxFloat(&g_nmax2[d], a);
}

__global__ __launch_bounds__(256) void k_expinit2(int N) {
    int n = blockIdx.x * blockDim.x + threadIdx.x;
    if (n >= N) return;
    float a = leaky(g_asrc2[n] + g_adst2[n]);
    float es = __expf(a - g_nmax2[n]);
    g_eself2[n] = es;
    g_den2[n] = es;
}

__global__ __launch_bounds__(256) void k_expsum2(const int* __restrict__ ei, int E) {
    int e = blockIdx.x * blockDim.x + threadIdx.x;
    if (e >= E) return;
    int d = ei[E + e];
    float ae = __expf(g_alpha2[e] - g_nmax2[d]);
    g_alpha2[e] = ae;
    atomicAdd(&g_den2[d], ae);
}

__global__ __launch_bounds__(256) void k_outinit(float* __restrict__ out,
                                                 const float* __restrict__ b2, int N) {
    int n = blockIdx.x * blockDim.x + threadIdx.x;
    if (n >= N) return;
    float r = 1.f / (g_den2[n] + EPS);
    float es = g_eself2[n];
    float2 hp = *(const float2*)&g_h2p[n * 2];
    out[n * 2]     = hp.x * es * r + b2[0];
    out[n * 2 + 1] = hp.y * es * r + b2[1];
    g_den2[n] = r;
}

__global__ __launch_bounds__(256) void k_agg2(const int* __restrict__ ei,
                                              float* __restrict__ out, int E) {
    int e = blockIdx.x * blockDim.x + threadIdx.x;
    if (e >= E) return;
    int s = ei[e], d = ei[E + e];
    float a = g_alpha2[e] * g_den2[d];
    float2 hp = *(const float2*)&g_h2p[s * 2];
    redAddV2(&out[d * 2], hp.x * a, hp.y * a);
}

// ------------------------ launch --------------------------------------------
extern "C" void kernel_launch(void* const* d_in, const int* in_sizes, int n_in,
                              void* d_out, int out_size) {
    const float* x   = (const float*)d_in[0];
    const int*   ei  = (const int*)  d_in[1];
    const float* ea  = (const float*)d_in[2];
    const float* W1  = (const float*)d_in[3];
    const float* We1 = (const float*)d_in[4];
    const float* as1 = (const float*)d_in[5];
    const float* ad1 = (const float*)d_in[6];
    const float* ae1 = (const float*)d_in[7];
    const float* b1  = (const float*)d_in[8];
    const float* W2  = (const float*)d_in[9];
    const float* We2 = (const float*)d_in[10];
    const float* as2 = (const float*)d_in[11];
    const float* ad2 = (const float*)d_in[12];
    const float* ae2 = (const float*)d_in[13];
    const float* b2  = (const float*)d_in[14];
    float* out = (float*)d_out;

    const int N = in_sizes[0] / 128;
    const int E = in_sizes[1] / 2;

    const int T = 256;
    const int gN   = (N + T - 1) / T;            // thread-per-node
    const int gNw  = (N * 32 + T - 1) / T;       // warp-per-node
    const int gE   = (E + T - 1) / T;            // thread-per-edge
    const int gEw  = (E * 32 + T - 1) / T;       // warp-per-edge
    const int gM   = (N + BM - 1) / BM;

    k_pre<<<1, 128>>>(We1, ae1, We2, ae2);
    k_gemm1<<<gM, 256>>>(x, W1, N);
    k_att1<<<gNw, T>>>(as1, ad1, N);

    k_init_max1<<<gN, T>>>(N);
    k_alpha1<<<gE, T>>>(ei, ea, E);
    k_expinit1<<<gN, T>>>(N);
    k_expsum1<<<gE, T>>>(ei, E);
    k_agginit1<<<gNw, T>>>(N);
    k_agg1<<<gEw, T>>>(ei, E);

    k_elu_proj2<<<gNw, T>>>(b1, W2, as2, ad2, N);

    k_init_max2<<<gN, T>>>(N);
    k_alpha2<<<gE, T>>>(ei, ea, E);
    k_expinit2<<<gN, T>>>(N);
    k_expsum2<<<gE, T>>>(ei, E);
    k_outinit<<<gN, T>>>(out, b2, N);
    k_agg2<<<gE, T>>>(ei, out, E);
}